// round 4
// baseline (speedup 1.0000x reference)
#include <cuda_runtime.h>
#include <math.h>

// Problem constants
#define T_STEPS 256
#define BATCH   1024
#define SEG     64
#define HID     128
#define G4      512          // 4*HID
#define K0      192          // SEG + HID (layer 0 fused input)
#define K1      256          // HID + HID (layer 1)
#define R       8            // batch rows per CTA
#define NCTA    (BATCH / R)  // 128 CTAs

// Scratch: preprocessed weights (gate-interleaved: [k][j][4] so thread j loads one float4)
__device__ float g_Wc0[K0 * HID * 4];   // 393 KB
__device__ float g_Wc1[K1 * HID * 4];   // 524 KB
__device__ float g_b0[G4];
__device__ float g_b1[G4];

// ---------------------------------------------------------------------------
// Prep: fold prelstm into layer-0 input weights, interleave gate columns.
//   gates0 = x_in @ W0^T + h @ w_hh0^T + (w_ih0@pre_b + b_ih0 + b_hh0)
//   W0 = w_ih0 @ pre_w  : [512, 64]
// Layout: g_Wc0[(k*HID + j)*4 + g] = weight for gate col n = g*128+j, input k.
//   k in [0,64)   : W0[n][k]
//   k in [64,192) : w_hh0[n][k-64]
// ---------------------------------------------------------------------------
__global__ void prep_kernel(
    const float* __restrict__ pre_w,  const float* __restrict__ pre_b,
    const float* __restrict__ w_ih0,  const float* __restrict__ w_hh0,
    const float* __restrict__ b_ih0,  const float* __restrict__ b_hh0,
    const float* __restrict__ w_ih1,  const float* __restrict__ w_hh1,
    const float* __restrict__ b_ih1,  const float* __restrict__ b_hh1)
{
    int idx = blockIdx.x * blockDim.x + threadIdx.x;
    int stride = gridDim.x * blockDim.x;

    for (int e = idx; e < K0 * G4; e += stride) {
        int k = e / G4;
        int n = e % G4;
        int g = n / HID;
        int j = n % HID;
        float v;
        if (k < SEG) {
            float s = 0.f;
            #pragma unroll 8
            for (int h = 0; h < HID; h++)
                s += w_ih0[n * HID + h] * pre_w[h * SEG + k];
            v = s;
        } else {
            v = w_hh0[n * HID + (k - SEG)];
        }
        g_Wc0[(k * HID + j) * 4 + g] = v;
    }

    for (int e = idx; e < K1 * G4; e += stride) {
        int k = e / G4;
        int n = e % G4;
        int g = n / HID;
        int j = n % HID;
        float v = (k < HID) ? w_ih1[n * HID + k] : w_hh1[n * HID + (k - HID)];
        g_Wc1[(k * HID + j) * 4 + g] = v;
    }

    for (int n = idx; n < G4; n += stride) {
        float s = 0.f;
        for (int h = 0; h < HID; h++)
            s += w_ih0[n * HID + h] * pre_b[h];
        g_b0[n] = s + b_ih0[n] + b_hh0[n];
        g_b1[n] = b_ih1[n] + b_hh1[n];
    }
}

__device__ __forceinline__ float sigmoidf_(float x) {
    return 1.f / (1.f + expf(-x));
}

// ---------------------------------------------------------------------------
// Fused persistent LSTM. Grid: 128 CTAs x 256 threads.
// CTA b handles batch rows [b*8, b*8+8). Thread (j = tid&127, half = tid>>7)
// owns hidden column j for rows half*4 .. half*4+3 (c state in registers,
// h state in SMEM so layer 1 and the recurrent matvec can read all of h).
// ---------------------------------------------------------------------------
__global__ __launch_bounds__(256, 1) void lstm_kernel(
    const float* __restrict__ x_in,   // [T, B, SEG]
    const float* __restrict__ h0in,   // [2, B, HID]
    const float* __restrict__ c0in,   // [2, B, HID]
    const float* __restrict__ post_w, // [1, HID]
    const float* __restrict__ post_b, // [1]
    float* __restrict__ out)          // pred[B] | h_t[2,B,H] | c_t[2,B,H]
{
    __shared__ float x_s[R][SEG];
    __shared__ float h0_s[R][HID];
    __shared__ float h1_s[R][HID];

    const int tid  = threadIdx.x;
    const int j    = tid & (HID - 1);
    const int half = tid >> 7;          // 0 or 1
    const int row0 = blockIdx.x * R;    // global batch row base
    const int rbase = half * 4;         // local row base for this thread

    float c0v[4], c1v[4];
    #pragma unroll
    for (int rr = 0; rr < 4; rr++) {
        int b = row0 + rbase + rr;
        c0v[rr] = c0in[0 * BATCH * HID + b * HID + j];
        c1v[rr] = c0in[1 * BATCH * HID + b * HID + j];
        h0_s[rbase + rr][j] = h0in[0 * BATCH * HID + b * HID + j];
        h1_s[rbase + rr][j] = h0in[1 * BATCH * HID + b * HID + j];
    }
    __syncthreads();

    const float4* __restrict__ W0p = (const float4*)g_Wc0;  // [K0*HID] float4
    const float4* __restrict__ W1p = (const float4*)g_Wc1;  // [K1*HID] float4

    float b0g[4], b1g[4];
    #pragma unroll
    for (int g = 0; g < 4; g++) {
        b0g[g] = g_b0[g * HID + j];
        b1g[g] = g_b1[g * HID + j];
    }

    float h0new[4], h1new[4];

    for (int t = 0; t < T_STEPS; t++) {
        // Stage x_t for this CTA's 8 rows (512 floats, 2 per thread)
        #pragma unroll
        for (int e = tid; e < R * SEG; e += 256) {
            int r = e >> 6;
            int s = e & 63;
            x_s[r][s] = x_in[((long)t * BATCH + (row0 + r)) * SEG + s];
        }
        __syncthreads();

        // ---------------- layer 0 ----------------
        float acc[4][4];
        #pragma unroll
        for (int g = 0; g < 4; g++)
            #pragma unroll
            for (int rr = 0; rr < 4; rr++)
                acc[g][rr] = b0g[g];

        #pragma unroll 8
        for (int k = 0; k < SEG; k++) {
            float4 w = W0p[k * HID + j];
            #pragma unroll
            for (int rr = 0; rr < 4; rr++) {
                float xv = x_s[rbase + rr][k];
                acc[0][rr] = fmaf(w.x, xv, acc[0][rr]);
                acc[1][rr] = fmaf(w.y, xv, acc[1][rr]);
                acc[2][rr] = fmaf(w.z, xv, acc[2][rr]);
                acc[3][rr] = fmaf(w.w, xv, acc[3][rr]);
            }
        }
        #pragma unroll 8
        for (int k = 0; k < HID; k++) {
            float4 w = W0p[(SEG + k) * HID + j];
            #pragma unroll
            for (int rr = 0; rr < 4; rr++) {
                float hv = h0_s[rbase + rr][k];
                acc[0][rr] = fmaf(w.x, hv, acc[0][rr]);
                acc[1][rr] = fmaf(w.y, hv, acc[1][rr]);
                acc[2][rr] = fmaf(w.z, hv, acc[2][rr]);
                acc[3][rr] = fmaf(w.w, hv, acc[3][rr]);
            }
        }
        #pragma unroll
        for (int rr = 0; rr < 4; rr++) {
            float ig = sigmoidf_(acc[0][rr]);
            float fg = sigmoidf_(acc[1][rr]);
            float gg = tanhf(acc[2][rr]);
            float og = sigmoidf_(acc[3][rr]);
            c0v[rr] = fg * c0v[rr] + ig * gg;
            h0new[rr] = og * tanhf(c0v[rr]);
        }
        __syncthreads();              // all reads of h0_s done
        #pragma unroll
        for (int rr = 0; rr < 4; rr++)
            h0_s[rbase + rr][j] = h0new[rr];
        __syncthreads();

        // ---------------- layer 1 ----------------
        #pragma unroll
        for (int g = 0; g < 4; g++)
            #pragma unroll
            for (int rr = 0; rr < 4; rr++)
                acc[g][rr] = b1g[g];

        #pragma unroll 8
        for (int k = 0; k < HID; k++) {
            float4 w = W1p[k * HID + j];
            #pragma unroll
            for (int rr = 0; rr < 4; rr++) {
                float hv = h0_s[rbase + rr][k];   // new h0_t
                acc[0][rr] = fmaf(w.x, hv, acc[0][rr]);
                acc[1][rr] = fmaf(w.y, hv, acc[1][rr]);
                acc[2][rr] = fmaf(w.z, hv, acc[2][rr]);
                acc[3][rr] = fmaf(w.w, hv, acc[3][rr]);
            }
        }
        #pragma unroll 8
        for (int k = 0; k < HID; k++) {
            float4 w = W1p[(HID + k) * HID + j];
            #pragma unroll
            for (int rr = 0; rr < 4; rr++) {
                float hv = h1_s[rbase + rr][k];   // previous h1
                acc[0][rr] = fmaf(w.x, hv, acc[0][rr]);
                acc[1][rr] = fmaf(w.y, hv, acc[1][rr]);
                acc[2][rr] = fmaf(w.z, hv, acc[2][rr]);
                acc[3][rr] = fmaf(w.w, hv, acc[3][rr]);
            }
        }
        #pragma unroll
        for (int rr = 0; rr < 4; rr++) {
            float ig = sigmoidf_(acc[0][rr]);
            float fg = sigmoidf_(acc[1][rr]);
            float gg = tanhf(acc[2][rr]);
            float og = sigmoidf_(acc[3][rr]);
            c1v[rr] = fg * c1v[rr] + ig * gg;
            h1new[rr] = og * tanhf(c1v[rr]);
        }
        __syncthreads();              // all reads of h1_s done
        #pragma unroll
        for (int rr = 0; rr < 4; rr++)
            h1_s[rbase + rr][j] = h1new[rr];
        __syncthreads();
    }

    // ---------------- outputs ----------------
    const int OH = BATCH;                    // h_t offset
    const int OC = BATCH + 2 * BATCH * HID;  // c_t offset
    #pragma unroll
    for (int rr = 0; rr < 4; rr++) {
        int b = row0 + rbase + rr;
        out[OH + 0 * BATCH * HID + b * HID + j] = h0new[rr];
        out[OH + 1 * BATCH * HID + b * HID + j] = h1new[rr];
        out[OC + 0 * BATCH * HID + b * HID + j] = c0v[rr];
        out[OC + 1 * BATCH * HID + b * HID + j] = c1v[rr];
    }

    // pred: one warp per row, deterministic shuffle reduce over relu(h1)*post_w
    int w    = tid >> 5;   // 8 warps = 8 rows
    int lane = tid & 31;
    float s = 0.f;
    #pragma unroll
    for (int jj = lane; jj < HID; jj += 32) {
        float hv = fmaxf(h1_s[w][jj], 0.f);
        s += hv * post_w[jj];
    }
    #pragma unroll
    for (int off = 16; off; off >>= 1)
        s += __shfl_xor_sync(0xffffffffu, s, off);
    if (lane == 0)
        out[row0 + w] = s + post_b[0];
}

extern "C" void kernel_launch(void* const* d_in, const int* in_sizes, int n_in,
                              void* d_out, int out_size)
{
    const float* x_in   = (const float*)d_in[0];
    const float* h0     = (const float*)d_in[1];
    const float* c0     = (const float*)d_in[2];
    const float* pre_w  = (const float*)d_in[3];
    const float* pre_b  = (const float*)d_in[4];
    const float* w_ih0  = (const float*)d_in[5];
    const float* w_hh0  = (const float*)d_in[6];
    const float* b_ih0  = (const float*)d_in[7];
    const float* b_hh0  = (const float*)d_in[8];
    const float* w_ih1  = (const float*)d_in[9];
    const float* w_hh1  = (const float*)d_in[10];
    const float* b_ih1  = (const float*)d_in[11];
    const float* b_hh1  = (const float*)d_in[12];
    const float* post_w = (const float*)d_in[13];
    const float* post_b = (const float*)d_in[14];
    float* out = (float*)d_out;

    prep_kernel<<<192, 256>>>(pre_w, pre_b, w_ih0, w_hh0, b_ih0, b_hh0,
                              w_ih1, w_hh1, b_ih1, b_hh1);
    lstm_kernel<<<NCTA, 256>>>(x_in, h0, c0, post_w, post_b, out);
}